// round 4
// baseline (speedup 1.0000x reference)
#include <cuda_runtime.h>
#include <cstdint>
#include <cstddef>

#define NN    50000
#define EE    800000
#define IN_F  128
#define HH    8
#define CC    32
#define HCF   256
#define GG    64
#define OUTF  64
#define NLAYERS 4

// ---------------- scratch (static device allocations; no cudaMalloc) ----------------
__device__ float g_hA[(size_t)NN * HCF];
__device__ float g_hB[(size_t)NN * HCF];
__device__ float g_q [(size_t)NN * HCF];
__device__ float g_k [(size_t)NN * HCF];
__device__ float g_v [(size_t)NN * HCF];
__device__ float g_p [(size_t)EE * HH];   // logits, then softmax numerators
__device__ float g_m [(size_t)NN * HH];   // segment max
__device__ float g_s [(size_t)NN * HH];   // segment sum
__device__ float g_pool[GG * HCF];
__device__ float g_cnt [GG];

// ---------------- helpers ----------------
__device__ __forceinline__ void atomicMaxFloat(float* addr, float val) {
    if (val >= 0.0f) atomicMax((int*)addr, __float_as_int(val));
    else             atomicMin((unsigned int*)addr, __float_as_uint(val));
}

__device__ __forceinline__ void redAdd4(float* addr, float a, float b, float c, float d) {
    asm volatile("red.global.add.v4.f32 [%0], {%1,%2,%3,%4};"
                 :: "l"(addr), "f"(a), "f"(b), "f"(c), "f"(d) : "memory");
}

// ---------------- fused 4-way SGEMM (q,k,v,skip) ----------------
// C[n][o] = sum_k relu?(A[n][k]) * W[k][o] + bias[o];  W is K x 256 row-major.
#define BM 128
#define BN 64
#define BK 16

__global__ __launch_bounds__(256) void sgemm4(
    const float* __restrict__ A, int K, int Nrows, int applyRelu,
    const float* __restrict__ W0, const float* __restrict__ W1,
    const float* __restrict__ W2, const float* __restrict__ W3,
    const float* __restrict__ b0, const float* __restrict__ b1,
    const float* __restrict__ b2, const float* __restrict__ b3,
    float* __restrict__ C0, float* __restrict__ C1,
    float* __restrict__ C2, float* __restrict__ C3)
{
    const float* W; const float* bias; float* C;
    switch (blockIdx.z) {
        case 0:  W = W0; bias = b0; C = C0; break;
        case 1:  W = W1; bias = b1; C = C1; break;
        case 2:  W = W2; bias = b2; C = C2; break;
        default: W = W3; bias = b3; C = C3; break;
    }

    __shared__ float As[BK][BM + 1];
    __shared__ float Bs[BK][BN];

    const int tx   = threadIdx.x;
    const int row0 = blockIdx.x * BM;
    const int col0 = blockIdx.y * BN;
    const int tr   = (tx >> 4) << 3;   // 0..120 step 8
    const int tc   = (tx & 15) << 2;   // 0..60  step 4

    float acc[8][4];
    #pragma unroll
    for (int i = 0; i < 8; i++)
        #pragma unroll
        for (int j = 0; j < 4; j++) acc[i][j] = 0.f;

    for (int k0 = 0; k0 < K; k0 += BK) {
        // load A tile (BM x BK), optional fused relu on input activations
        #pragma unroll
        for (int i = tx; i < BM * BK; i += 256) {
            int m = i >> 4, kk = i & 15;
            int r = row0 + m;
            float a = (r < Nrows) ? __ldg(&A[(size_t)r * K + k0 + kk]) : 0.f;
            if (applyRelu) a = fmaxf(a, 0.f);
            As[kk][m] = a;
        }
        // load W tile (BK x BN)
        #pragma unroll
        for (int i = tx; i < BK * BN; i += 256) {
            int kk = i >> 6, n = i & 63;
            Bs[kk][n] = __ldg(&W[(size_t)(k0 + kk) * HCF + col0 + n]);
        }
        __syncthreads();

        #pragma unroll
        for (int kk = 0; kk < BK; kk++) {
            float a[8], b[4];
            #pragma unroll
            for (int i = 0; i < 8; i++) a[i] = As[kk][tr + i];
            float4 bb = *(const float4*)&Bs[kk][tc];
            b[0] = bb.x; b[1] = bb.y; b[2] = bb.z; b[3] = bb.w;
            #pragma unroll
            for (int i = 0; i < 8; i++)
                #pragma unroll
                for (int j = 0; j < 4; j++)
                    acc[i][j] += a[i] * b[j];
        }
        __syncthreads();
    }

    float b4[4];
    #pragma unroll
    for (int j = 0; j < 4; j++) b4[j] = __ldg(&bias[col0 + tc + j]);

    #pragma unroll
    for (int i = 0; i < 8; i++) {
        int r = row0 + tr + i;
        if (r < Nrows) {
            float4 outv;
            outv.x = acc[i][0] + b4[0];
            outv.y = acc[i][1] + b4[1];
            outv.z = acc[i][2] + b4[2];
            outv.w = acc[i][3] + b4[3];
            *(float4*)&C[(size_t)r * HCF + col0 + tc] = outv;
        }
    }
}

// ---------------- per-layer scratch init (segment max/sum) ----------------
__global__ void init_ms_kernel() {
    int i = blockIdx.x * blockDim.x + threadIdx.x;
    if (i < NN * HH) {
        g_m[i] = -__int_as_float(0x7f800000);  // -inf
        g_s[i] = 0.0f;
    }
}

// ---------------- pass A: per-edge logits + segment max ----------------
__global__ __launch_bounds__(256) void edge_logits_kernel(
    const float* __restrict__ q, const float* __restrict__ k,
    const int* __restrict__ srcp, const int* __restrict__ dstp)
{
    int warp = (blockIdx.x * blockDim.x + threadIdx.x) >> 5;
    int lane = threadIdx.x & 31;
    if (warp >= EE) return;
    int s = srcp[warp], d = dstp[warp];

    const float4* qp = (const float4*)(q + (size_t)d * HCF) + lane * 2;
    const float4* kp = (const float4*)(k + (size_t)s * HCF) + lane * 2;
    float4 q0 = qp[0], q1 = qp[1];
    float4 k0 = kp[0], k1 = kp[1];
    float part = q0.x*k0.x + q0.y*k0.y + q0.z*k0.z + q0.w*k0.w
               + q1.x*k1.x + q1.y*k1.y + q1.z*k1.z + q1.w*k1.w;
    part += __shfl_xor_sync(0xffffffffu, part, 1);
    part += __shfl_xor_sync(0xffffffffu, part, 2);
    if ((lane & 3) == 0) {
        int h = lane >> 2;
        float lg = part * 0.17677669529663689f;  // 1/sqrt(32)
        g_p[(size_t)warp * HH + h] = lg;
        atomicMaxFloat(&g_m[(size_t)d * HH + h], lg);
    }
}

// ---------------- pass B: exp + segment sum ----------------
__global__ __launch_bounds__(256) void edge_exp_kernel(const int* __restrict__ dstp) {
    size_t idx = (size_t)blockIdx.x * blockDim.x + threadIdx.x;
    if (idx >= (size_t)EE * HH) return;
    int e = (int)(idx >> 3);
    int h = (int)(idx & 7);
    int d = dstp[e];
    float pv = __expf(g_p[idx] - g_m[(size_t)d * HH + h]);
    g_p[idx] = pv;
    atomicAdd(&g_s[(size_t)d * HH + h], pv);
}

// ---------------- pass C: weighted aggregation (scatter-add) ----------------
__global__ __launch_bounds__(256) void edge_agg_kernel(
    const float* __restrict__ v,
    const int* __restrict__ srcp, const int* __restrict__ dstp,
    float* __restrict__ out)
{
    int warp = (blockIdx.x * blockDim.x + threadIdx.x) >> 5;
    int lane = threadIdx.x & 31;
    if (warp >= EE) return;
    int s = srcp[warp], d = dstp[warp];
    int h = lane >> 2;
    float alpha = g_p[(size_t)warp * HH + h] / (g_s[(size_t)d * HH + h] + 1e-16f);

    const float4* vp = (const float4*)(v + (size_t)s * HCF) + lane * 2;
    float4 v0 = vp[0], v1 = vp[1];
    float* op = out + (size_t)d * HCF + lane * 8;
    redAdd4(op,     alpha*v0.x, alpha*v0.y, alpha*v0.z, alpha*v0.w);
    redAdd4(op + 4, alpha*v1.x, alpha*v1.y, alpha*v1.z, alpha*v1.w);
}

// ---------------- pooling (with fused relu on the final hidden state) ----------------
__global__ void zero_pool_kernel() {
    int i = blockIdx.x * blockDim.x + threadIdx.x;
    if (i < GG * HCF) g_pool[i] = 0.0f;
    if (i < GG)       g_cnt[i]  = 0.0f;
}

__global__ __launch_bounds__(256) void pool_kernel(
    const float* __restrict__ h, const int* __restrict__ batch)
{
    int n = blockIdx.x;
    int b = batch[n];
    float val = fmaxf(h[(size_t)n * HCF + threadIdx.x], 0.0f);  // fused relu
    atomicAdd(&g_pool[b * HCF + threadIdx.x], val);
    if (threadIdx.x == 0) atomicAdd(&g_cnt[b], 1.0f);
}

// ---------------- final projection ----------------
__global__ void final_kernel(const float* __restrict__ Wfc,
                             const float* __restrict__ bfc,
                             float* __restrict__ out)
{
    int g = blockIdx.x;      // 0..63
    int o = threadIdx.x;     // 0..63
    float inv = 1.0f / fmaxf(g_cnt[g], 1.0f);
    float acc = 0.0f;
    #pragma unroll 8
    for (int i = 0; i < HCF; i++)
        acc += g_pool[g * HCF + i] * Wfc[i * OUTF + o];
    out[g * OUTF + o] = acc * inv + bfc[o];
}

// ---------------- launch ----------------
extern "C" void kernel_launch(void* const* d_in, const int* in_sizes, int n_in,
                              void* d_out, int out_size)
{
    const float* x      = (const float*)d_in[0];
    const int*   ei     = (const int*)  d_in[1];
    const int*   batch  = (const int*)  d_in[2];
    const float* Wq0 = (const float*)d_in[3];  const float* bq0 = (const float*)d_in[4];
    const float* Wk0 = (const float*)d_in[5];  const float* bk0 = (const float*)d_in[6];
    const float* Wv0 = (const float*)d_in[7];  const float* bv0 = (const float*)d_in[8];
    const float* Ws0 = (const float*)d_in[9];  const float* bs0 = (const float*)d_in[10];
    const float* Wq  = (const float*)d_in[11]; const float* bq  = (const float*)d_in[12];
    const float* Wk  = (const float*)d_in[13]; const float* bk  = (const float*)d_in[14];
    const float* Wv  = (const float*)d_in[15]; const float* bv  = (const float*)d_in[16];
    const float* Ws  = (const float*)d_in[17]; const float* bs  = (const float*)d_in[18];
    const float* Wfc = (const float*)d_in[19]; const float* bfc = (const float*)d_in[20];

    const int* srcp = ei;
    const int* dstp = ei + EE;

    float *hA, *hB, *q, *k, *v;
    cudaGetSymbolAddress((void**)&hA, g_hA);
    cudaGetSymbolAddress((void**)&hB, g_hB);
    cudaGetSymbolAddress((void**)&q,  g_q);
    cudaGetSymbolAddress((void**)&k,  g_k);
    cudaGetSymbolAddress((void**)&v,  g_v);

    const float* hin = x;
    int K = IN_F;
    float* bufs[2] = { hA, hB };

    for (int l = 0; l < NLAYERS; l++) {
        const float *Wq_l, *Wk_l, *Wv_l, *Ws_l, *bq_l, *bk_l, *bv_l, *bs_l;
        if (l == 0) {
            Wq_l = Wq0; Wk_l = Wk0; Wv_l = Wv0; Ws_l = Ws0;
            bq_l = bq0; bk_l = bk0; bv_l = bv0; bs_l = bs0;
        } else {
            size_t wo = (size_t)(l - 1) * HCF * HCF;
            size_t bo = (size_t)(l - 1) * HCF;
            Wq_l = Wq + wo; Wk_l = Wk + wo; Wv_l = Wv + wo; Ws_l = Ws + wo;
            bq_l = bq + bo; bk_l = bk + bo; bv_l = bv + bo; bs_l = bs + bo;
        }
        float* hout = bufs[l & 1];

        dim3 ggrid((NN + BM - 1) / BM, HCF / BN, 4);
        // relu of the previous layer's output is fused into the A-tile load
        sgemm4<<<ggrid, 256>>>(hin, K, NN, (l > 0) ? 1 : 0,
                               Wq_l, Wk_l, Wv_l, Ws_l,
                               bq_l, bk_l, bv_l, bs_l,
                               q, k, v, hout);

        init_ms_kernel<<<(NN * HH + 255) / 256, 256>>>();
        edge_logits_kernel<<<EE / 8, 256>>>(q, k, srcp, dstp);
        edge_exp_kernel<<<(EE * HH) / 256, 256>>>(dstp);
        edge_agg_kernel<<<EE / 8, 256>>>(v, srcp, dstp, hout);

        hin = hout;
        K = HCF;
    }

    zero_pool_kernel<<<(GG * HCF + 255) / 256, 256>>>();
    pool_kernel<<<NN, 256>>>(hin, batch);  // relu fused here for the last layer
    final_kernel<<<GG, OUTF>>>(Wfc, bfc, (float*)d_out);
}

// round 6
// speedup vs baseline: 1.2453x; 1.2453x over previous
#include <cuda_runtime.h>
#include <cstdint>
#include <cstddef>

#define NN    50000
#define EE    800000
#define IN_F  128
#define HH    8
#define CC    32
#define HCF   256
#define GG    64
#define OUTF  64
#define NLAYERS 4

// ---------------- scratch (static device allocations; no cudaMalloc) ----------------
__device__ float g_hA[(size_t)NN * HCF];
__device__ float g_hB[(size_t)NN * HCF];
__device__ float g_q [(size_t)NN * HCF];
__device__ float g_k [(size_t)NN * HCF];
__device__ float g_v [(size_t)NN * HCF];
__device__ float g_p [(size_t)EE * HH];   // logits, then softmax numerators
__device__ float g_m [(size_t)NN * HH];   // segment max
__device__ float g_s [(size_t)NN * HH];   // segment sum
__device__ float g_pool[GG * HCF];
__device__ float g_cnt [GG];

// ---------------- helpers ----------------
__device__ __forceinline__ void atomicMaxFloat(float* addr, float val) {
    if (val >= 0.0f) atomicMax((int*)addr, __float_as_int(val));
    else             atomicMin((unsigned int*)addr, __float_as_uint(val));
}

__device__ __forceinline__ void redAdd4(float* addr, float a, float b, float c, float d) {
    asm volatile("red.global.add.v4.f32 [%0], {%1,%2,%3,%4};"
                 :: "l"(addr), "f"(a), "f"(b), "f"(c), "f"(d) : "memory");
}

// split x into tf32 hi + tf32 lo (hi+lo ~ x to ~2^-22)
__device__ __forceinline__ void tf32_split(float x, float& hi, float& lo) {
    uint32_t h; asm("cvt.rna.tf32.f32 %0, %1;" : "=r"(h) : "f"(x));
    hi = __uint_as_float(h);
    float r = x - hi;
    uint32_t l; asm("cvt.rna.tf32.f32 %0, %1;" : "=r"(l) : "f"(r));
    lo = __uint_as_float(l);
}

#define MMA_TF32(c, a0, a1, a2, a3, b0, b1)                                  \
    asm volatile("mma.sync.aligned.m16n8k8.row.col.f32.tf32.tf32.f32 "       \
                 "{%0,%1,%2,%3}, {%4,%5,%6,%7}, {%8,%9}, {%0,%1,%2,%3};"     \
                 : "+f"((c)[0]), "+f"((c)[1]), "+f"((c)[2]), "+f"((c)[3])    \
                 : "r"(a0), "r"(a1), "r"(a2), "r"(a3), "r"(b0), "r"(b1))

// ---------------- fused 4-way split-TF32 tensor-core GEMM (q,k,v,skip) ----------------
// C[n][o] = sum_k relu?(A[n][k]) * W[k][o] + bias[o];  W is K x 256 row-major.
#define BM 128
#define BN 64
#define BK 32
#define AS_STRIDE 36   // (4*lq + lr) banks all distinct for A frag loads
#define BS_STRIDE 72   // (8*lr + lq) banks all distinct for B frag loads
#define A_TILE (BM * AS_STRIDE)
#define B_TILE (BK * BS_STRIDE)
#define SMEM_FLOATS (2 * A_TILE + 2 * B_TILE)
#define SMEM_BYTES  (SMEM_FLOATS * 4)

__global__ __launch_bounds__(256, 2) void sgemm4_tf32(
    const float* __restrict__ A, int K, int Nrows, int applyRelu,
    const float* __restrict__ W0, const float* __restrict__ W1,
    const float* __restrict__ W2, const float* __restrict__ W3,
    const float* __restrict__ b0p, const float* __restrict__ b1p,
    const float* __restrict__ b2p, const float* __restrict__ b3p,
    float* __restrict__ C0, float* __restrict__ C1,
    float* __restrict__ C2, float* __restrict__ C3)
{
    const float* W; const float* bias; float* C;
    switch (blockIdx.z) {
        case 0:  W = W0; bias = b0p; C = C0; break;
        case 1:  W = W1; bias = b1p; C = C1; break;
        case 2:  W = W2; bias = b2p; C = C2; break;
        default: W = W3; bias = b3p; C = C3; break;
    }

    extern __shared__ float smem[];
    float* As_h = smem;
    float* As_l = As_h + A_TILE;
    float* Bs_h = As_l + A_TILE;
    float* Bs_l = Bs_h + B_TILE;

    const int tx   = threadIdx.x;
    const int lane = tx & 31;
    const int warp = tx >> 5;
    const int wm   = warp & 3;   // 4 warps along M (32 rows each)
    const int wn   = warp >> 2;  // 2 warps along N (32 cols each)
    const int row0 = blockIdx.x * BM;
    const int col0 = blockIdx.y * BN;

    const int lq = lane >> 2;    // 0..7
    const int lr = lane & 3;     // 0..3

    float acc[2][4][4];
    #pragma unroll
    for (int mt = 0; mt < 2; mt++)
        #pragma unroll
        for (int nt = 0; nt < 4; nt++)
            #pragma unroll
            for (int r = 0; r < 4; r++) acc[mt][nt][r] = 0.f;

    for (int k0 = 0; k0 < K; k0 += BK) {
        // ---- A tile: 128 rows x 32 k, split into hi/lo, layout [m][k] ----
        #pragma unroll
        for (int it = 0; it < 4; it++) {
            int r  = (tx >> 3) + it * 32;
            int kq = (tx & 7) * 4;
            int grow = row0 + r;
            float4 va = make_float4(0.f, 0.f, 0.f, 0.f);
            if (grow < Nrows) va = *(const float4*)&A[(size_t)grow * K + k0 + kq];
            if (applyRelu) {
                va.x = fmaxf(va.x, 0.f); va.y = fmaxf(va.y, 0.f);
                va.z = fmaxf(va.z, 0.f); va.w = fmaxf(va.w, 0.f);
            }
            float4 h4, l4;
            tf32_split(va.x, h4.x, l4.x);
            tf32_split(va.y, h4.y, l4.y);
            tf32_split(va.z, h4.z, l4.z);
            tf32_split(va.w, h4.w, l4.w);
            *(float4*)&As_h[r * AS_STRIDE + kq] = h4;
            *(float4*)&As_l[r * AS_STRIDE + kq] = l4;
        }
        // ---- B tile: 32 k x 64 n, split hi/lo, layout [k][n] ----
        #pragma unroll
        for (int it = 0; it < 2; it++) {
            int kk = (tx >> 4) + it * 16;
            int nq = (tx & 15) * 4;
            float4 vb = *(const float4*)&W[(size_t)(k0 + kk) * HCF + col0 + nq];
            float4 h4, l4;
            tf32_split(vb.x, h4.x, l4.x);
            tf32_split(vb.y, h4.y, l4.y);
            tf32_split(vb.z, h4.z, l4.z);
            tf32_split(vb.w, h4.w, l4.w);
            *(float4*)&Bs_h[kk * BS_STRIDE + nq] = h4;
            *(float4*)&Bs_l[kk * BS_STRIDE + nq] = l4;
        }
        __syncthreads();

        #pragma unroll
        for (int ks = 0; ks < BK / 8; ks++) {
            int kk = ks * 8 + lr;

            uint32_t ah[2][4], al[2][4];
            #pragma unroll
            for (int mt = 0; mt < 2; mt++) {
                int m = wm * 32 + mt * 16 + lq;
                ah[mt][0] = __float_as_uint(As_h[(size_t)m       * AS_STRIDE + kk]);
                ah[mt][1] = __float_as_uint(As_h[(size_t)(m + 8) * AS_STRIDE + kk]);
                ah[mt][2] = __float_as_uint(As_h[(size_t)m       * AS_STRIDE + kk + 4]);
                ah[mt][3] = __float_as_uint(As_h[(size_t)(m + 8) * AS_STRIDE + kk + 4]);
                al[mt][0] = __float_as_uint(As_l[(size_t)m       * AS_STRIDE + kk]);
                al[mt][1] = __float_as_uint(As_l[(size_t)(m + 8) * AS_STRIDE + kk]);
                al[mt][2] = __float_as_uint(As_l[(size_t)m       * AS_STRIDE + kk + 4]);
                al[mt][3] = __float_as_uint(As_l[(size_t)(m + 8) * AS_STRIDE + kk + 4]);
            }

            #pragma unroll
            for (int nt = 0; nt < 4; nt++) {
                int n = wn * 32 + nt * 8 + lq;
                uint32_t bh0 = __float_as_uint(Bs_h[(size_t)kk       * BS_STRIDE + n]);
                uint32_t bh1 = __float_as_uint(Bs_h[(size_t)(kk + 4) * BS_STRIDE + n]);
                uint32_t bl0 = __float_as_uint(Bs_l[(size_t)kk       * BS_STRIDE + n]);
                uint32_t bl1 = __float_as_uint(Bs_l[(size_t)(kk + 4) * BS_STRIDE + n]);
                #pragma unroll
                for (int mt = 0; mt < 2; mt++) {
                    MMA_TF32(acc[mt][nt], ah[mt][0], ah[mt][1], ah[mt][2], ah[mt][3], bh0, bh1);
                    MMA_TF32(acc[mt][nt], al[mt][0], al[mt][1], al[mt][2], al[mt][3], bh0, bh1);
                    MMA_TF32(acc[mt][nt], ah[mt][0], ah[mt][1], ah[mt][2], ah[mt][3], bl0, bl1);
                }
            }
        }
        __syncthreads();
    }

    // ---- epilogue: bias + store ----
    #pragma unroll
    for (int mt = 0; mt < 2; mt++) {
        int m = row0 + wm * 32 + mt * 16 + lq;
        #pragma unroll
        for (int nt = 0; nt < 4; nt++) {
            int n = col0 + wn * 32 + nt * 8 + lr * 2;
            float bb0 = __ldg(&bias[n]);
            float bb1 = __ldg(&bias[n + 1]);
            if (m < Nrows) {
                float2 o0 = make_float2(acc[mt][nt][0] + bb0, acc[mt][nt][1] + bb1);
                *(float2*)&C[(size_t)m * HCF + n] = o0;
            }
            if (m + 8 < Nrows) {
                float2 o1 = make_float2(acc[mt][nt][2] + bb0, acc[mt][nt][3] + bb1);
                *(float2*)&C[(size_t)(m + 8) * HCF + n] = o1;
            }
        }
    }
}

// ---------------- per-layer scratch init (segment max/sum) ----------------
__global__ void init_ms_kernel() {
    int i = blockIdx.x * blockDim.x + threadIdx.x;
    if (i < NN * HH) {
        g_m[i] = -__int_as_float(0x7f800000);  // -inf
        g_s[i] = 0.0f;
    }
}

// ---------------- pass A: per-edge logits + segment max ----------------
__global__ __launch_bounds__(256) void edge_logits_kernel(
    const float* __restrict__ q, const float* __restrict__ k,
    const int* __restrict__ srcp, const int* __restrict__ dstp)
{
    int warp = (blockIdx.x * blockDim.x + threadIdx.x) >> 5;
    int lane = threadIdx.x & 31;
    if (warp >= EE) return;
    int s = srcp[warp], d = dstp[warp];

    const float4* qp = (const float4*)(q + (size_t)d * HCF) + lane * 2;
    const float4* kp = (const float4*)(k + (size_t)s * HCF) + lane * 2;
    float4 q0 = qp[0], q1 = qp[1];
    float4 k0 = kp[0], k1 = kp[1];
    float part = q0.x*k0.x + q0.y*k0.y + q0.z*k0.z + q0.w*k0.w
               + q1.x*k1.x + q1.y*k1.y + q1.z*k1.z + q1.w*k1.w;
    part += __shfl_xor_sync(0xffffffffu, part, 1);
    part += __shfl_xor_sync(0xffffffffu, part, 2);
    if ((lane & 3) == 0) {
        int h = lane >> 2;
        float lg = part * 0.17677669529663689f;  // 1/sqrt(32)
        g_p[(size_t)warp * HH + h] = lg;
        atomicMaxFloat(&g_m[(size_t)d * HH + h], lg);
    }
}

// ---------------- pass B: exp + segment sum ----------------
__global__ __launch_bounds__(256) void edge_exp_kernel(const int* __restrict__ dstp) {
    size_t idx = (size_t)blockIdx.x * blockDim.x + threadIdx.x;
    if (idx >= (size_t)EE * HH) return;
    int e = (int)(idx >> 3);
    int h = (int)(idx & 7);
    int d = dstp[e];
    float pv = __expf(g_p[idx] - g_m[(size_t)d * HH + h]);
    g_p[idx] = pv;
    atomicAdd(&g_s[(size_t)d * HH + h], pv);
}

// ---------------- pass C: weighted aggregation (scatter-add) ----------------
__global__ __launch_bounds__(256) void edge_agg_kernel(
    const float* __restrict__ v,
    const int* __restrict__ srcp, const int* __restrict__ dstp,
    float* __restrict__ out)
{
    int warp = (blockIdx.x * blockDim.x + threadIdx.x) >> 5;
    int lane = threadIdx.x & 31;
    if (warp >= EE) return;
    int s = srcp[warp], d = dstp[warp];
    int h = lane >> 2;
    float alpha = g_p[(size_t)warp * HH + h] / (g_s[(size_t)d * HH + h] + 1e-16f);

    const float4* vp = (const float4*)(v + (size_t)s * HCF) + lane * 2;
    float4 v0 = vp[0], v1 = vp[1];
    float* op = out + (size_t)d * HCF + lane * 8;
    redAdd4(op,     alpha*v0.x, alpha*v0.y, alpha*v0.z, alpha*v0.w);
    redAdd4(op + 4, alpha*v1.x, alpha*v1.y, alpha*v1.z, alpha*v1.w);
}

// ---------------- pooling (with fused relu on the final hidden state) ----------------
__global__ void zero_pool_kernel() {
    int i = blockIdx.x * blockDim.x + threadIdx.x;
    if (i < GG * HCF) g_pool[i] = 0.0f;
    if (i < GG)       g_cnt[i]  = 0.0f;
}

__global__ __launch_bounds__(256) void pool_kernel(
    const float* __restrict__ h, const int* __restrict__ batch)
{
    int n = blockIdx.x;
    int b = batch[n];
    float val = fmaxf(h[(size_t)n * HCF + threadIdx.x], 0.0f);  // fused relu
    atomicAdd(&g_pool[b * HCF + threadIdx.x], val);
    if (threadIdx.x == 0) atomicAdd(&g_cnt[b], 1.0f);
}

// ---------------- final projection ----------------
__global__ void final_kernel(const float* __restrict__ Wfc,
                             const float* __restrict__ bfc,
                             float* __restrict__ out)
{
    int g = blockIdx.x;      // 0..63
    int o = threadIdx.x;     // 0..63
    float inv = 1.0f / fmaxf(g_cnt[g], 1.0f);
    float acc = 0.0f;
    #pragma unroll 8
    for (int i = 0; i < HCF; i++)
        acc += g_pool[g * HCF + i] * Wfc[i * OUTF + o];
    out[g * OUTF + o] = acc * inv + bfc[o];
}

// ---------------- launch ----------------
extern "C" void kernel_launch(void* const* d_in, const int* in_sizes, int n_in,
                              void* d_out, int out_size)
{
    const float* x      = (const float*)d_in[0];
    const int*   ei     = (const int*)  d_in[1];
    const int*   batch  = (const int*)  d_in[2];
    const float* Wq0 = (const float*)d_in[3];  const float* bq0 = (const float*)d_in[4];
    const float* Wk0 = (const float*)d_in[5];  const float* bk0 = (const float*)d_in[6];
    const float* Wv0 = (const float*)d_in[7];  const float* bv0 = (const float*)d_in[8];
    const float* Ws0 = (const float*)d_in[9];  const float* bs0 = (const float*)d_in[10];
    const float* Wq  = (const float*)d_in[11]; const float* bq  = (const float*)d_in[12];
    const float* Wk  = (const float*)d_in[13]; const float* bk  = (const float*)d_in[14];
    const float* Wv  = (const float*)d_in[15]; const float* bv  = (const float*)d_in[16];
    const float* Ws  = (const float*)d_in[17]; const float* bs  = (const float*)d_in[18];
    const float* Wfc = (const float*)d_in[19]; const float* bfc = (const float*)d_in[20];

    const int* srcp = ei;
    const int* dstp = ei + EE;

    // idempotent, host-side only; no static guard (harness forbids call-count state)
    cudaFuncSetAttribute(sgemm4_tf32,
                         cudaFuncAttributeMaxDynamicSharedMemorySize, SMEM_BYTES);

    float *hA, *hB, *q, *k, *v;
    cudaGetSymbolAddress((void**)&hA, g_hA);
    cudaGetSymbolAddress((void**)&hB, g_hB);
    cudaGetSymbolAddress((void**)&q,  g_q);
    cudaGetSymbolAddress((void**)&k,  g_k);
    cudaGetSymbolAddress((void**)&v,  g_v);

    const float* hin = x;
    int K = IN_F;
    float* bufs[2] = { hA, hB };

    for (int l = 0; l < NLAYERS; l++) {
        const float *Wq_l, *Wk_l, *Wv_l, *Ws_l, *bq_l, *bk_l, *bv_l, *bs_l;
        if (l == 0) {
            Wq_l = Wq0; Wk_l = Wk0; Wv_l = Wv0; Ws_l = Ws0;
            bq_l = bq0; bk_l = bk0; bv_l = bv0; bs_l = bs0;
        } else {
            size_t wo = (size_t)(l - 1) * HCF * HCF;
            size_t bo = (size_t)(l - 1) * HCF;
            Wq_l = Wq + wo; Wk_l = Wk + wo; Wv_l = Wv + wo; Ws_l = Ws + wo;
            bq_l = bq + bo; bk_l = bk + bo; bv_l = bv + bo; bs_l = bs + bo;
        }
        float* hout = bufs[l & 1];

        dim3 ggrid((NN + BM - 1) / BM, HCF / BN, 4);
        sgemm4_tf32<<<ggrid, 256, SMEM_BYTES>>>(hin, K, NN, (l > 0) ? 1 : 0,
                               Wq_l, Wk_l, Wv_l, Ws_l,
                               bq_l, bk_l, bv_l, bs_l,
                               q, k, v, hout);

        init_ms_kernel<<<(NN * HH + 255) / 256, 256>>>();
        edge_logits_kernel<<<EE / 8, 256>>>(q, k, srcp, dstp);
        edge_exp_kernel<<<(EE * HH) / 256, 256>>>(dstp);
        edge_agg_kernel<<<EE / 8, 256>>>(v, srcp, dstp, hout);

        hin = hout;
        K = HCF;
    }

    zero_pool_kernel<<<(GG * HCF + 255) / 256, 256>>>();
    pool_kernel<<<NN, 256>>>(hin, batch);  // relu fused here for the last layer
    final_kernel<<<GG, OUTF>>>(Wfc, bfc, (float*)d_out);
}

// round 13
// speedup vs baseline: 1.7638x; 1.4164x over previous
#include <cuda_runtime.h>
#include <cstdint>
#include <cstddef>

#define NN    50000
#define EE    800000
#define IN_F  128
#define HH    8
#define CC    32
#define HCF   256
#define GG    64
#define OUTF  64
#define NLAYERS 4

#define SCAN_NBLK ((NN + 255) / 256)   // 196

// ---------------- scratch (static device allocations; no cudaMalloc) ----------------
__device__ float g_hA[(size_t)NN * HCF];
__device__ float g_hB[(size_t)NN * HCF];
__device__ float g_q [(size_t)NN * HCF];
__device__ float g_k [(size_t)NN * HCF];
__device__ float g_v [(size_t)NN * HCF];
__device__ float g_pool[GG * HCF];
__device__ float g_cnt [GG];
// CSR by destination
__device__ int g_deg[NN];
__device__ int g_cursor[NN];
__device__ int g_off[NN + 1];
__device__ int g_blocksum[SCAN_NBLK];
__device__ int g_blockoff[SCAN_NBLK];
__device__ int g_csr_src[EE];

// split x into tf32 hi + tf32 lo (hi+lo ~ x to ~2^-22)
__device__ __forceinline__ void tf32_split(float x, float& hi, float& lo) {
    uint32_t h; asm("cvt.rna.tf32.f32 %0, %1;" : "=r"(h) : "f"(x));
    hi = __uint_as_float(h);
    float r = x - hi;
    uint32_t l; asm("cvt.rna.tf32.f32 %0, %1;" : "=r"(l) : "f"(r));
    lo = __uint_as_float(l);
}

#define MMA_TF32(c, a0, a1, a2, a3, b0, b1)                                  \
    asm volatile("mma.sync.aligned.m16n8k8.row.col.f32.tf32.tf32.f32 "       \
                 "{%0,%1,%2,%3}, {%4,%5,%6,%7}, {%8,%9}, {%0,%1,%2,%3};"     \
                 : "+f"((c)[0]), "+f"((c)[1]), "+f"((c)[2]), "+f"((c)[3])    \
                 : "r"(a0), "r"(a1), "r"(a2), "r"(a3), "r"(b0), "r"(b1))

// ---------------- fused 4-way split-TF32 tensor-core GEMM (q,k,v,skip) ----------------
#define BM 128
#define BN 64
#define BK 32
#define AS_STRIDE 36
#define BS_STRIDE 72
#define A_TILE (BM * AS_STRIDE)
#define B_TILE (BK * BS_STRIDE)
#define SMEM_BYTES ((2 * A_TILE + 2 * B_TILE) * 4)

__global__ __launch_bounds__(256, 2) void sgemm4_tf32(
    const float* __restrict__ A, int K, int Nrows, int applyRelu,
    const float* __restrict__ W0, const float* __restrict__ W1,
    const float* __restrict__ W2, const float* __restrict__ W3,
    const float* __restrict__ b0p, const float* __restrict__ b1p,
    const float* __restrict__ b2p, const float* __restrict__ b3p,
    float* __restrict__ C0, float* __restrict__ C1,
    float* __restrict__ C2, float* __restrict__ C3)
{
    const float* W; const float* bias; float* C;
    switch (blockIdx.z) {
        case 0:  W = W0; bias = b0p; C = C0; break;
        case 1:  W = W1; bias = b1p; C = C1; break;
        case 2:  W = W2; bias = b2p; C = C2; break;
        default: W = W3; bias = b3p; C = C3; break;
    }

    extern __shared__ float smem[];
    float* As_h = smem;
    float* As_l = As_h + A_TILE;
    float* Bs_h = As_l + A_TILE;
    float* Bs_l = Bs_h + B_TILE;

    const int tx   = threadIdx.x;
    const int lane = tx & 31;
    const int warp = tx >> 5;
    const int wm   = warp & 3;
    const int wn   = warp >> 2;
    const int row0 = blockIdx.x * BM;
    const int col0 = blockIdx.y * BN;
    const int lq = lane >> 2;
    const int lr = lane & 3;

    float acc[2][4][4];
    #pragma unroll
    for (int mt = 0; mt < 2; mt++)
        #pragma unroll
        for (int nt = 0; nt < 4; nt++)
            #pragma unroll
            for (int r = 0; r < 4; r++) acc[mt][nt][r] = 0.f;

    for (int k0 = 0; k0 < K; k0 += BK) {
        #pragma unroll
        for (int it = 0; it < 4; it++) {
            int r  = (tx >> 3) + it * 32;
            int kq = (tx & 7) * 4;
            int grow = row0 + r;
            float4 va = make_float4(0.f, 0.f, 0.f, 0.f);
            if (grow < Nrows) va = *(const float4*)&A[(size_t)grow * K + k0 + kq];
            if (applyRelu) {
                va.x = fmaxf(va.x, 0.f); va.y = fmaxf(va.y, 0.f);
                va.z = fmaxf(va.z, 0.f); va.w = fmaxf(va.w, 0.f);
            }
            float4 h4, l4;
            tf32_split(va.x, h4.x, l4.x);
            tf32_split(va.y, h4.y, l4.y);
            tf32_split(va.z, h4.z, l4.z);
            tf32_split(va.w, h4.w, l4.w);
            *(float4*)&As_h[r * AS_STRIDE + kq] = h4;
            *(float4*)&As_l[r * AS_STRIDE + kq] = l4;
        }
        #pragma unroll
        for (int it = 0; it < 2; it++) {
            int kk = (tx >> 4) + it * 16;
            int nq = (tx & 15) * 4;
            float4 vb = *(const float4*)&W[(size_t)(k0 + kk) * HCF + col0 + nq];
            float4 h4, l4;
            tf32_split(vb.x, h4.x, l4.x);
            tf32_split(vb.y, h4.y, l4.y);
            tf32_split(vb.z, h4.z, l4.z);
            tf32_split(vb.w, h4.w, l4.w);
            *(float4*)&Bs_h[kk * BS_STRIDE + nq] = h4;
            *(float4*)&Bs_l[kk * BS_STRIDE + nq] = l4;
        }
        __syncthreads();

        #pragma unroll
        for (int ks = 0; ks < BK / 8; ks++) {
            int kk = ks * 8 + lr;
            uint32_t ah[2][4], al[2][4];
            #pragma unroll
            for (int mt = 0; mt < 2; mt++) {
                int m = wm * 32 + mt * 16 + lq;
                ah[mt][0] = __float_as_uint(As_h[(size_t)m       * AS_STRIDE + kk]);
                ah[mt][1] = __float_as_uint(As_h[(size_t)(m + 8) * AS_STRIDE + kk]);
                ah[mt][2] = __float_as_uint(As_h[(size_t)m       * AS_STRIDE + kk + 4]);
                ah[mt][3] = __float_as_uint(As_h[(size_t)(m + 8) * AS_STRIDE + kk + 4]);
                al[mt][0] = __float_as_uint(As_l[(size_t)m       * AS_STRIDE + kk]);
                al[mt][1] = __float_as_uint(As_l[(size_t)(m + 8) * AS_STRIDE + kk]);
                al[mt][2] = __float_as_uint(As_l[(size_t)m       * AS_STRIDE + kk + 4]);
                al[mt][3] = __float_as_uint(As_l[(size_t)(m + 8) * AS_STRIDE + kk + 4]);
            }
            #pragma unroll
            for (int nt = 0; nt < 4; nt++) {
                int n = wn * 32 + nt * 8 + lq;
                uint32_t bh0 = __float_as_uint(Bs_h[(size_t)kk       * BS_STRIDE + n]);
                uint32_t bh1 = __float_as_uint(Bs_h[(size_t)(kk + 4) * BS_STRIDE + n]);
                uint32_t bl0 = __float_as_uint(Bs_l[(size_t)kk       * BS_STRIDE + n]);
                uint32_t bl1 = __float_as_uint(Bs_l[(size_t)(kk + 4) * BS_STRIDE + n]);
                #pragma unroll
                for (int mt = 0; mt < 2; mt++) {
                    MMA_TF32(acc[mt][nt], ah[mt][0], ah[mt][1], ah[mt][2], ah[mt][3], bh0, bh1);
                    MMA_TF32(acc[mt][nt], al[mt][0], al[mt][1], al[mt][2], al[mt][3], bh0, bh1);
                    MMA_TF32(acc[mt][nt], ah[mt][0], ah[mt][1], ah[mt][2], ah[mt][3], bl0, bl1);
                }
            }
        }
        __syncthreads();
    }

    #pragma unroll
    for (int mt = 0; mt < 2; mt++) {
        int m = row0 + wm * 32 + mt * 16 + lq;
        #pragma unroll
        for (int nt = 0; nt < 4; nt++) {
            int n = col0 + wn * 32 + nt * 8 + lr * 2;
            float bb0 = __ldg(&bias[n]);
            float bb1 = __ldg(&bias[n + 1]);
            if (m < Nrows) {
                float2 o0 = make_float2(acc[mt][nt][0] + bb0, acc[mt][nt][1] + bb1);
                *(float2*)&C[(size_t)m * HCF + n] = o0;
            }
            if (m + 8 < Nrows) {
                float2 o1 = make_float2(acc[mt][nt][2] + bb0, acc[mt][nt][3] + bb1);
                *(float2*)&C[(size_t)(m + 8) * HCF + n] = o1;
            }
        }
    }
}

// ---------------- CSR build ----------------
__global__ void csr_zero_kernel() {
    int i = blockIdx.x * blockDim.x + threadIdx.x;
    if (i < NN) { g_deg[i] = 0; g_cursor[i] = 0; }
}

__global__ void csr_hist_kernel(const int* __restrict__ dstp) {
    int e = blockIdx.x * blockDim.x + threadIdx.x;
    if (e < EE) atomicAdd(&g_deg[dstp[e]], 1);
}

__global__ void csr_scan1_kernel() {
    __shared__ int sm[256];
    int t = threadIdx.x;
    int i = blockIdx.x * 256 + t;
    int val = (i < NN) ? g_deg[i] : 0;
    sm[t] = val;
    __syncthreads();
    #pragma unroll
    for (int o = 1; o < 256; o <<= 1) {
        int x = (t >= o) ? sm[t - o] : 0;
        __syncthreads();
        sm[t] += x;
        __syncthreads();
    }
    if (i < NN) g_off[i] = sm[t] - val;         // exclusive within block
    if (t == 255) g_blocksum[blockIdx.x] = sm[t];
}

__global__ void csr_scan2_kernel() {
    __shared__ int sm[256];
    int t = threadIdx.x;
    int val = (t < SCAN_NBLK) ? g_blocksum[t] : 0;
    sm[t] = val;
    __syncthreads();
    #pragma unroll
    for (int o = 1; o < 256; o <<= 1) {
        int x = (t >= o) ? sm[t - o] : 0;
        __syncthreads();
        sm[t] += x;
        __syncthreads();
    }
    if (t < SCAN_NBLK) g_blockoff[t] = sm[t] - val;  // exclusive
}

// block b of 256 covers indices [b*256, b*256+255]
__global__ void csr_scan3b_kernel() {
    int i = blockIdx.x * 256 + threadIdx.x;
    if (i < NN) g_off[i] += g_blockoff[blockIdx.x];
    if (i == 0) g_off[NN] = EE;
}

__global__ void csr_fill_kernel(const int* __restrict__ srcp, const int* __restrict__ dstp) {
    int e = blockIdx.x * blockDim.x + threadIdx.x;
    if (e < EE) {
        int d = dstp[e];
        int pos = g_off[d] + atomicAdd(&g_cursor[d], 1);
        g_csr_src[pos] = srcp[e];
    }
}

// ---------------- fused per-dst online-softmax attention ----------------
// one warp per dst node: q[d] resident in registers, single pass over neighbors,
// flash-style running (m, s, acc); no atomics; out[d] += acc/s (out holds skip).
__global__ __launch_bounds__(256) void attn_fused_kernel(
    const float* __restrict__ q, const float* __restrict__ k,
    const float* __restrict__ v, float* __restrict__ out)
{
    int w    = (blockIdx.x * blockDim.x + threadIdx.x) >> 5;
    int lane = threadIdx.x & 31;
    if (w >= NN) return;

    int beg = g_off[w];
    int end = g_off[w + 1];
    if (beg == end) return;   // no in-edges: out stays = skip

    const float sc = 0.17677669529663689f;  // 1/sqrt(32)
    const float4* qp = (const float4*)(q + (size_t)w * HCF) + lane * 2;
    float4 q0 = qp[0], q1 = qp[1];
    q0.x *= sc; q0.y *= sc; q0.z *= sc; q0.w *= sc;
    q1.x *= sc; q1.y *= sc; q1.z *= sc; q1.w *= sc;

    float m = -__int_as_float(0x7f800000);  // -inf
    float s = 0.f;
    float4 acc0 = make_float4(0.f, 0.f, 0.f, 0.f);
    float4 acc1 = make_float4(0.f, 0.f, 0.f, 0.f);

    for (int i = beg; i < end; i++) {
        int sn = g_csr_src[i];
        const float4* kp = (const float4*)(k + (size_t)sn * HCF) + lane * 2;
        const float4* vp = (const float4*)(v + (size_t)sn * HCF) + lane * 2;
        float4 k0 = kp[0], k1 = kp[1];
        float4 v0 = vp[0], v1 = vp[1];

        float part = q0.x*k0.x + q0.y*k0.y + q0.z*k0.z + q0.w*k0.w
                   + q1.x*k1.x + q1.y*k1.y + q1.z*k1.z + q1.w*k1.w;
        part += __shfl_xor_sync(0xffffffffu, part, 1);
        part += __shfl_xor_sync(0xffffffffu, part, 2);
        // all 4 lanes of this head group now hold the head logit

        float mn = fmaxf(m, part);
        float c  = __expf(m - mn);     // first iter: exp(-inf) = 0
        float p  = __expf(part - mn);
        s = s * c + p;
        acc0.x = acc0.x * c + p * v0.x;
        acc0.y = acc0.y * c + p * v0.y;
        acc0.z = acc0.z * c + p * v0.z;
        acc0.w = acc0.w * c + p * v0.w;
        acc1.x = acc1.x * c + p * v1.x;
        acc1.y = acc1.y * c + p * v1.y;
        acc1.z = acc1.z * c + p * v1.z;
        acc1.w = acc1.w * c + p * v1.w;
        m = mn;
    }

    float inv = 1.f / (s + 1e-16f);
    float* op = out + (size_t)w * HCF + lane * 8;
    float4 o0 = *(float4*)op;
    float4 o1 = *(float4*)(op + 4);
    o0.x += acc0.x * inv; o0.y += acc0.y * inv;
    o0.z += acc0.z * inv; o0.w += acc0.w * inv;
    o1.x += acc1.x * inv; o1.y += acc1.y * inv;
    o1.z += acc1.z * inv; o1.w += acc1.w * inv;
    *(float4*)op       = o0;
    *(float4*)(op + 4) = o1;
}

// ---------------- pooling (with fused relu on the final hidden state) ----------------
__global__ void zero_pool_kernel() {
    int i = blockIdx.x * blockDim.x + threadIdx.x;
    if (i < GG * HCF) g_pool[i] = 0.0f;
    if (i < GG)       g_cnt[i]  = 0.0f;
}

__global__ __launch_bounds__(256) void pool_kernel(
    const float* __restrict__ h, const int* __restrict__ batch)
{
    int n = blockIdx.x;
    int b = batch[n];
    float val = fmaxf(h[(size_t)n * HCF + threadIdx.x], 0.0f);  // fused relu
    atomicAdd(&g_pool[b * HCF + threadIdx.x], val);
    if (threadIdx.x == 0) atomicAdd(&g_cnt[b], 1.0f);
}

// ---------------- final projection ----------------
__global__ void final_kernel(const float* __restrict__ Wfc,
                             const float* __restrict__ bfc,
                             float* __restrict__ out)
{
    int g = blockIdx.x;
    int o = threadIdx.x;
    float inv = 1.0f / fmaxf(g_cnt[g], 1.0f);
    float acc = 0.0f;
    #pragma unroll 8
    for (int i = 0; i < HCF; i++)
        acc += g_pool[g * HCF + i] * Wfc[i * OUTF + o];
    out[g * OUTF + o] = acc * inv + bfc[o];
}

// ---------------- launch ----------------
extern "C" void kernel_launch(void* const* d_in, const int* in_sizes, int n_in,
                              void* d_out, int out_size)
{
    const float* x      = (const float*)d_in[0];
    const int*   ei     = (const int*)  d_in[1];
    const int*   batch  = (const int*)  d_in[2];
    const float* Wq0 = (const float*)d_in[3];  const float* bq0 = (const float*)d_in[4];
    const float* Wk0 = (const float*)d_in[5];  const float* bk0 = (const float*)d_in[6];
    const float* Wv0 = (const float*)d_in[7];  const float* bv0 = (const float*)d_in[8];
    const float* Ws0 = (const float*)d_in[9];  const float* bs0 = (const float*)d_in[10];
    const float* Wq  = (const float*)d_in[11]; const float* bq  = (const float*)d_in[12];
    const float* Wk  = (const float*)d_in[13]; const float* bk  = (const float*)d_in[14];
    const float* Wv  = (const float*)d_in[15]; const float* bv  = (const float*)d_in[16];
    const float* Ws  = (const float*)d_in[17]; const float* bs  = (const float*)d_in[18];
    const float* Wfc = (const float*)d_in[19]; const float* bfc = (const float*)d_in[20];

    const int* srcp = ei;
    const int* dstp = ei + EE;

    cudaFuncSetAttribute(sgemm4_tf32,
                         cudaFuncAttributeMaxDynamicSharedMemorySize, SMEM_BYTES);

    float *hA, *hB, *q, *k, *v;
    cudaGetSymbolAddress((void**)&hA, g_hA);
    cudaGetSymbolAddress((void**)&hB, g_hB);
    cudaGetSymbolAddress((void**)&q,  g_q);
    cudaGetSymbolAddress((void**)&k,  g_k);
    cudaGetSymbolAddress((void**)&v,  g_v);

    // ---- build CSR once per call (graph is layer-invariant) ----
    csr_zero_kernel<<<(NN + 255) / 256, 256>>>();
    csr_hist_kernel<<<(EE + 255) / 256, 256>>>(dstp);
    csr_scan1_kernel<<<SCAN_NBLK, 256>>>();
    csr_scan2_kernel<<<1, 256>>>();
    csr_scan3b_kernel<<<SCAN_NBLK, 256>>>();
    csr_fill_kernel<<<(EE + 255) / 256, 256>>>(srcp, dstp);

    const float* hin = x;
    int K = IN_F;
    float* bufs[2] = { hA, hB };

    for (int l = 0; l < NLAYERS; l++) {
        const float *Wq_l, *Wk_l, *Wv_l, *Ws_l, *bq_l, *bk_l, *bv_l, *bs_l;
        if (l == 0) {
            Wq_l = Wq0; Wk_l = Wk0; Wv_l = Wv0; Ws_l = Ws0;
            bq_l = bq0; bk_l = bk0; bv_l = bv0; bs_l = bs0;
        } else {
            size_t wo = (size_t)(l - 1) * HCF * HCF;
            size_t bo = (size_t)(l - 1) * HCF;
            Wq_l = Wq + wo; Wk_l = Wk + wo; Wv_l = Wv + wo; Ws_l = Ws + wo;
            bq_l = bq + bo; bk_l = bk + bo; bv_l = bv + bo; bs_l = bs + bo;
        }
        float* hout = bufs[l & 1];

        dim3 ggrid((NN + BM - 1) / BM, HCF / BN, 4);
        sgemm4_tf32<<<ggrid, 256, SMEM_BYTES>>>(hin, K, NN, (l > 0) ? 1 : 0,
                               Wq_l, Wk_l, Wv_l, Ws_l,
                               bq_l, bk_l, bv_l, bs_l,
                               q, k, v, hout);

        attn_fused_kernel<<<(NN * 32 + 255) / 256, 256>>>(q, k, v, hout);

        hin = hout;
        K = HCF;
    }

    zero_pool_kernel<<<(GG * HCF + 255) / 256, 256>>>();
    pool_kernel<<<NN, 256>>>(hin, batch);  // relu fused here for the last layer
    final_kernel<<<GG, OUTF>>>(Wfc, bfc, (float*)d_out);
}

// round 14
// speedup vs baseline: 1.7717x; 1.0045x over previous
#include <cuda_runtime.h>
#include <cstdint>
#include <cstddef>

#define NN    50000
#define EE    800000
#define IN_F  128
#define HH    8
#define CC    32
#define HCF   256
#define GG    64
#define OUTF  64
#define NLAYERS 4

#define SCAN_NBLK ((NN + 255) / 256)   // 196

// ---------------- scratch (static device allocations; no cudaMalloc) ----------------
__device__ float g_hA[(size_t)NN * HCF];
__device__ float g_hB[(size_t)NN * HCF];
__device__ float g_q [(size_t)NN * HCF];
__device__ float g_k [(size_t)NN * HCF];
__device__ float g_v [(size_t)NN * HCF];
__device__ float g_pool[GG * HCF];
__device__ float g_cnt [GG];
// CSR by destination
__device__ int g_deg[NN];
__device__ int g_cursor[NN];
__device__ int g_off[NN + 1];
__device__ int g_blocksum[SCAN_NBLK];
__device__ int g_blockoff[SCAN_NBLK];
__device__ int g_csr_src[EE];

// split x into tf32 hi + tf32 lo (hi+lo ~ x to ~2^-22)
__device__ __forceinline__ void tf32_split(float x, float& hi, float& lo) {
    uint32_t h; asm("cvt.rna.tf32.f32 %0, %1;" : "=r"(h) : "f"(x));
    hi = __uint_as_float(h);
    float r = x - hi;
    uint32_t l; asm("cvt.rna.tf32.f32 %0, %1;" : "=r"(l) : "f"(r));
    lo = __uint_as_float(l);
}

#define MMA_TF32(c, a0, a1, a2, a3, b0, b1)                                  \
    asm volatile("mma.sync.aligned.m16n8k8.row.col.f32.tf32.tf32.f32 "       \
                 "{%0,%1,%2,%3}, {%4,%5,%6,%7}, {%8,%9}, {%0,%1,%2,%3};"     \
                 : "+f"((c)[0]), "+f"((c)[1]), "+f"((c)[2]), "+f"((c)[3])    \
                 : "r"(a0), "r"(a1), "r"(a2), "r"(a3), "r"(b0), "r"(b1))

// ---------------- fused 4-way split-TF32 tensor-core GEMM (q,k,v,skip) ----------------
#define BM 128
#define BN 64
#define BK 32
#define AS_STRIDE 36
#define BS_STRIDE 72
#define A_TILE (BM * AS_STRIDE)
#define B_TILE (BK * BS_STRIDE)
#define SMEM_BYTES ((2 * A_TILE + 2 * B_TILE) * 4)

__global__ __launch_bounds__(256, 2) void sgemm4_tf32(
    const float* __restrict__ A, int K, int Nrows, int applyRelu,
    const float* __restrict__ W0, const float* __restrict__ W1,
    const float* __restrict__ W2, const float* __restrict__ W3,
    const float* __restrict__ b0p, const float* __restrict__ b1p,
    const float* __restrict__ b2p, const float* __restrict__ b3p,
    float* __restrict__ C0, float* __restrict__ C1,
    float* __restrict__ C2, float* __restrict__ C3)
{
    const float* W; const float* bias; float* C;
    switch (blockIdx.z) {
        case 0:  W = W0; bias = b0p; C = C0; break;
        case 1:  W = W1; bias = b1p; C = C1; break;
        case 2:  W = W2; bias = b2p; C = C2; break;
        default: W = W3; bias = b3p; C = C3; break;
    }

    extern __shared__ float smem[];
    float* As_h = smem;
    float* As_l = As_h + A_TILE;
    float* Bs_h = As_l + A_TILE;
    float* Bs_l = Bs_h + B_TILE;

    const int tx   = threadIdx.x;
    const int lane = tx & 31;
    const int warp = tx >> 5;
    const int wm   = warp & 3;
    const int wn   = warp >> 2;
    const int row0 = blockIdx.x * BM;
    const int col0 = blockIdx.y * BN;
    const int lq = lane >> 2;
    const int lr = lane & 3;

    float acc[2][4][4];
    #pragma unroll
    for (int mt = 0; mt < 2; mt++)
        #pragma unroll
        for (int nt = 0; nt < 4; nt++)
            #pragma unroll
            for (int r = 0; r < 4; r++) acc[mt][nt][r] = 0.f;

    for (int k0 = 0; k0 < K; k0 += BK) {
        #pragma unroll
        for (int it = 0; it < 4; it++) {
            int r  = (tx >> 3) + it * 32;
            int kq = (tx & 7) * 4;
            int grow = row0 + r;
            float4 va = make_float4(0.f, 0.f, 0.f, 0.f);
            if (grow < Nrows) va = *(const float4*)&A[(size_t)grow * K + k0 + kq];
            if (applyRelu) {
                va.x = fmaxf(va.x, 0.f); va.y = fmaxf(va.y, 0.f);
                va.z = fmaxf(va.z, 0.f); va.w = fmaxf(va.w, 0.f);
            }
            float4 h4, l4;
            tf32_split(va.x, h4.x, l4.x);
            tf32_split(va.y, h4.y, l4.y);
            tf32_split(va.z, h4.z, l4.z);
            tf32_split(va.w, h4.w, l4.w);
            *(float4*)&As_h[r * AS_STRIDE + kq] = h4;
            *(float4*)&As_l[r * AS_STRIDE + kq] = l4;
        }
        #pragma unroll
        for (int it = 0; it < 2; it++) {
            int kk = (tx >> 4) + it * 16;
            int nq = (tx & 15) * 4;
            float4 vb = *(const float4*)&W[(size_t)(k0 + kk) * HCF + col0 + nq];
            float4 h4, l4;
            tf32_split(vb.x, h4.x, l4.x);
            tf32_split(vb.y, h4.y, l4.y);
            tf32_split(vb.z, h4.z, l4.z);
            tf32_split(vb.w, h4.w, l4.w);
            *(float4*)&Bs_h[kk * BS_STRIDE + nq] = h4;
            *(float4*)&Bs_l[kk * BS_STRIDE + nq] = l4;
        }
        __syncthreads();

        #pragma unroll
        for (int ks = 0; ks < BK / 8; ks++) {
            int kk = ks * 8 + lr;
            uint32_t ah[2][4], al[2][4];
            #pragma unroll
            for (int mt = 0; mt < 2; mt++) {
                int m = wm * 32 + mt * 16 + lq;
                ah[mt][0] = __float_as_uint(As_h[(size_t)m       * AS_STRIDE + kk]);
                ah[mt][1] = __float_as_uint(As_h[(size_t)(m + 8) * AS_STRIDE + kk]);
                ah[mt][2] = __float_as_uint(As_h[(size_t)m       * AS_STRIDE + kk + 4]);
                ah[mt][3] = __float_as_uint(As_h[(size_t)(m + 8) * AS_STRIDE + kk + 4]);
                al[mt][0] = __float_as_uint(As_l[(size_t)m       * AS_STRIDE + kk]);
                al[mt][1] = __float_as_uint(As_l[(size_t)(m + 8) * AS_STRIDE + kk]);
                al[mt][2] = __float_as_uint(As_l[(size_t)m       * AS_STRIDE + kk + 4]);
                al[mt][3] = __float_as_uint(As_l[(size_t)(m + 8) * AS_STRIDE + kk + 4]);
            }
            #pragma unroll
            for (int nt = 0; nt < 4; nt++) {
                int n = wn * 32 + nt * 8 + lq;
                uint32_t bh0 = __float_as_uint(Bs_h[(size_t)kk       * BS_STRIDE + n]);
                uint32_t bh1 = __float_as_uint(Bs_h[(size_t)(kk + 4) * BS_STRIDE + n]);
                uint32_t bl0 = __float_as_uint(Bs_l[(size_t)kk       * BS_STRIDE + n]);
                uint32_t bl1 = __float_as_uint(Bs_l[(size_t)(kk + 4) * BS_STRIDE + n]);
                #pragma unroll
                for (int mt = 0; mt < 2; mt++) {
                    MMA_TF32(acc[mt][nt], ah[mt][0], ah[mt][1], ah[mt][2], ah[mt][3], bh0, bh1);
                    MMA_TF32(acc[mt][nt], al[mt][0], al[mt][1], al[mt][2], al[mt][3], bh0, bh1);
                    MMA_TF32(acc[mt][nt], ah[mt][0], ah[mt][1], ah[mt][2], ah[mt][3], bl0, bl1);
                }
            }
        }
        __syncthreads();
    }

    #pragma unroll
    for (int mt = 0; mt < 2; mt++) {
        int m = row0 + wm * 32 + mt * 16 + lq;
        #pragma unroll
        for (int nt = 0; nt < 4; nt++) {
            int n = col0 + wn * 32 + nt * 8 + lr * 2;
            float bb0 = __ldg(&bias[n]);
            float bb1 = __ldg(&bias[n + 1]);
            if (m < Nrows) {
                float2 o0 = make_float2(acc[mt][nt][0] + bb0, acc[mt][nt][1] + bb1);
                *(float2*)&C[(size_t)m * HCF + n] = o0;
            }
            if (m + 8 < Nrows) {
                float2 o1 = make_float2(acc[mt][nt][2] + bb0, acc[mt][nt][3] + bb1);
                *(float2*)&C[(size_t)(m + 8) * HCF + n] = o1;
            }
        }
    }
}

// ---------------- CSR build ----------------
__global__ void csr_zero_kernel() {
    int i = blockIdx.x * blockDim.x + threadIdx.x;
    if (i < NN) { g_deg[i] = 0; g_cursor[i] = 0; }
}

__global__ void csr_hist_kernel(const int* __restrict__ dstp) {
    int e = blockIdx.x * blockDim.x + threadIdx.x;
    if (e < EE) atomicAdd(&g_deg[dstp[e]], 1);
}

__global__ void csr_scan1_kernel() {
    __shared__ int sm[256];
    int t = threadIdx.x;
    int i = blockIdx.x * 256 + t;
    int val = (i < NN) ? g_deg[i] : 0;
    sm[t] = val;
    __syncthreads();
    #pragma unroll
    for (int o = 1; o < 256; o <<= 1) {
        int x = (t >= o) ? sm[t - o] : 0;
        __syncthreads();
        sm[t] += x;
        __syncthreads();
    }
    if (i < NN) g_off[i] = sm[t] - val;         // exclusive within block
    if (t == 255) g_blocksum[blockIdx.x] = sm[t];
}

__global__ void csr_scan2_kernel() {
    __shared__ int sm[256];
    int t = threadIdx.x;
    int val = (t < SCAN_NBLK) ? g_blocksum[t] : 0;
    sm[t] = val;
    __syncthreads();
    #pragma unroll
    for (int o = 1; o < 256; o <<= 1) {
        int x = (t >= o) ? sm[t - o] : 0;
        __syncthreads();
        sm[t] += x;
        __syncthreads();
    }
    if (t < SCAN_NBLK) g_blockoff[t] = sm[t] - val;  // exclusive
}

// block b of 256 covers indices [b*256, b*256+255]
__global__ void csr_scan3b_kernel() {
    int i = blockIdx.x * 256 + threadIdx.x;
    if (i < NN) g_off[i] += g_blockoff[blockIdx.x];
    if (i == 0) g_off[NN] = EE;
}

__global__ void csr_fill_kernel(const int* __restrict__ srcp, const int* __restrict__ dstp) {
    int e = blockIdx.x * blockDim.x + threadIdx.x;
    if (e < EE) {
        int d = dstp[e];
        int pos = g_off[d] + atomicAdd(&g_cursor[d], 1);
        g_csr_src[pos] = srcp[e];
    }
}

// ---------------- fused per-dst online-softmax attention (2-edge ILP) ----------------
// one warp per dst node: q[d] resident in registers, single pass over neighbors,
// flash-style running (m, s, acc); edge pairs share one rescale; no atomics.
__global__ __launch_bounds__(256) void attn_fused_kernel(
    const float* __restrict__ q, const float* __restrict__ k,
    const float* __restrict__ v, float* __restrict__ out)
{
    int w    = (blockIdx.x * blockDim.x + threadIdx.x) >> 5;
    int lane = threadIdx.x & 31;
    if (w >= NN) return;

    int beg = g_off[w];
    int end = g_off[w + 1];
    if (beg == end) return;   // no in-edges: out stays = skip

    const float sc = 0.17677669529663689f;  // 1/sqrt(32)
    const float4* qp = (const float4*)(q + (size_t)w * HCF) + lane * 2;
    float4 q0 = qp[0], q1 = qp[1];
    q0.x *= sc; q0.y *= sc; q0.z *= sc; q0.w *= sc;
    q1.x *= sc; q1.y *= sc; q1.z *= sc; q1.w *= sc;

    float m = -__int_as_float(0x7f800000);  // -inf
    float s = 0.f;
    float4 acc0 = make_float4(0.f, 0.f, 0.f, 0.f);
    float4 acc1 = make_float4(0.f, 0.f, 0.f, 0.f);

    int i = beg;
    // ---- paired edges: 8 gathers in flight, one rescale per pair ----
    for (; i + 1 < end; i += 2) {
        int sa = g_csr_src[i];
        int sb = g_csr_src[i + 1];
        const float4* kap = (const float4*)(k + (size_t)sa * HCF) + lane * 2;
        const float4* vap = (const float4*)(v + (size_t)sa * HCF) + lane * 2;
        const float4* kbp = (const float4*)(k + (size_t)sb * HCF) + lane * 2;
        const float4* vbp = (const float4*)(v + (size_t)sb * HCF) + lane * 2;
        float4 ka0 = kap[0], ka1 = kap[1];
        float4 kb0 = kbp[0], kb1 = kbp[1];
        float4 va0 = vap[0], va1 = vap[1];
        float4 vb0 = vbp[0], vb1 = vbp[1];

        float pa = q0.x*ka0.x + q0.y*ka0.y + q0.z*ka0.z + q0.w*ka0.w
                 + q1.x*ka1.x + q1.y*ka1.y + q1.z*ka1.z + q1.w*ka1.w;
        float pb = q0.x*kb0.x + q0.y*kb0.y + q0.z*kb0.z + q0.w*kb0.w
                 + q1.x*kb1.x + q1.y*kb1.y + q1.z*kb1.z + q1.w*kb1.w;
        pa += __shfl_xor_sync(0xffffffffu, pa, 1);
        pa += __shfl_xor_sync(0xffffffffu, pa, 2);
        pb += __shfl_xor_sync(0xffffffffu, pb, 1);
        pb += __shfl_xor_sync(0xffffffffu, pb, 2);

        float mn = fmaxf(m, fmaxf(pa, pb));
        float c  = __expf(m - mn);       // first pair: exp(-inf) = 0
        float ea = __expf(pa - mn);
        float eb = __expf(pb - mn);
        s = s * c + ea + eb;
        acc0.x = acc0.x * c + ea * va0.x + eb * vb0.x;
        acc0.y = acc0.y * c + ea * va0.y + eb * vb0.y;
        acc0.z = acc0.z * c + ea * va0.z + eb * vb0.z;
        acc0.w = acc0.w * c + ea * va0.w + eb * vb0.w;
        acc1.x = acc1.x * c + ea * va1.x + eb * vb1.x;
        acc1.y = acc1.y * c + ea * va1.y + eb * vb1.y;
        acc1.z = acc1.z * c + ea * va1.z + eb * vb1.z;
        acc1.w = acc1.w * c + ea * va1.w + eb * vb1.w;
        m = mn;
    }
    // ---- tail edge ----
    if (i < end) {
        int sn = g_csr_src[i];
        const float4* kp = (const float4*)(k + (size_t)sn * HCF) + lane * 2;
        const float4* vp = (const float4*)(v + (size_t)sn * HCF) + lane * 2;
        float4 k0 = kp[0], k1 = kp[1];
        float4 v0 = vp[0], v1 = vp[1];

        float part = q0.x*k0.x + q0.y*k0.y + q0.z*k0.z + q0.w*k0.w
                   + q1.x*k1.x + q1.y*k1.y + q1.z*k1.z + q1.w*k1.w;
        part += __shfl_xor_sync(0xffffffffu, part, 1);
        part += __shfl_xor_sync(0xffffffffu, part, 2);

        float mn = fmaxf(m, part);
        float c  = __expf(m - mn);
        float p  = __expf(part - mn);
        s = s * c + p;
        acc0.x = acc0.x * c + p * v0.x;
        acc0.y = acc0.y * c + p * v0.y;
        acc0.z = acc0.z * c + p * v0.z;
        acc0.w = acc0.w * c + p * v0.w;
        acc1.x = acc1.x * c + p * v1.x;
        acc1.y = acc1.y * c + p * v1.y;
        acc1.z = acc1.z * c + p * v1.z;
        acc1.w = acc1.w * c + p * v1.w;
        m = mn;
    }

    float inv = 1.f / (s + 1e-16f);
    float* op = out + (size_t)w * HCF + lane * 8;
    float4 o0 = *(float4*)op;
    float4 o1 = *(float4*)(op + 4);
    o0.x += acc0.x * inv; o0.y += acc0.y * inv;
    o0.z += acc0.z * inv; o0.w += acc0.w * inv;
    o1.x += acc1.x * inv; o1.y += acc1.y * inv;
    o1.z += acc1.z * inv; o1.w += acc1.w * inv;
    *(float4*)op       = o0;
    *(float4*)(op + 4) = o1;
}

// ---------------- pooling (with fused relu on the final hidden state) ----------------
__global__ void zero_pool_kernel() {
    int i = blockIdx.x * blockDim.x + threadIdx.x;
    if (i < GG * HCF) g_pool[i] = 0.0f;
    if (i < GG)       g_cnt[i]  = 0.0f;
}

__global__ __launch_bounds__(256) void pool_kernel(
    const float* __restrict__ h, const int* __restrict__ batch)
{
    int n = blockIdx.x;
    int b = batch[n];
    float val = fmaxf(h[(size_t)n * HCF + threadIdx.x], 0.0f);  // fused relu
    atomicAdd(&g_pool[b * HCF + threadIdx.x], val);
    if (threadIdx.x == 0) atomicAdd(&g_cnt[b], 1.0f);
}

// ---------------- final projection ----------------
__global__ void final_kernel(const float* __restrict__ Wfc,
                             const float* __restrict__ bfc,
                             float* __restrict__ out)
{
    int g = blockIdx.x;
    int o = threadIdx.x;
    float inv = 1.0f / fmaxf(g_cnt[g], 1.0f);
    float acc = 0.0f;
    #pragma unroll 8
    for (int i = 0; i < HCF; i++)
        acc += g_pool[g * HCF + i] * Wfc[i * OUTF + o];
    out[g * OUTF + o] = acc * inv + bfc[o];
}

// ---------------- launch ----------------
extern "C" void kernel_launch(void* const* d_in, const int* in_sizes, int n_in,
                              void* d_out, int out_size)
{
    const float* x      = (const float*)d_in[0];
    const int*   ei     = (const int*)  d_in[1];
    const int*   batch  = (const int*)  d_in[2];
    const float* Wq0 = (const float*)d_in[3];  const float* bq0 = (const float*)d_in[4];
    const float* Wk0 = (const float*)d_in[5];  const float* bk0 = (const float*)d_in[6];
    const float* Wv0 = (const float*)d_in[7];  const float* bv0 = (const float*)d_in[8];
    const float* Ws0 = (const float*)d_in[9];  const float* bs0 = (const float*)d_in[10];
    const float* Wq  = (const float*)d_in[11]; const float* bq  = (const float*)d_in[12];
    const float* Wk  = (const float*)d_in[13]; const float* bk  = (const float*)d_in[14];
    const float* Wv  = (const float*)d_in[15]; const float* bv  = (const float*)d_in[16];
    const float* Ws  = (const float*)d_in[17]; const float* bs  = (const float*)d_in[18];
    const float* Wfc = (const float*)d_in[19]; const float* bfc = (const float*)d_in[20];

    const int* srcp = ei;
    const int* dstp = ei + EE;

    cudaFuncSetAttribute(sgemm4_tf32,
                         cudaFuncAttributeMaxDynamicSharedMemorySize, SMEM_BYTES);

    float *hA, *hB, *q, *k, *v;
    cudaGetSymbolAddress((void**)&hA, g_hA);
    cudaGetSymbolAddress((void**)&hB, g_hB);
    cudaGetSymbolAddress((void**)&q,  g_q);
    cudaGetSymbolAddress((void**)&k,  g_k);
    cudaGetSymbolAddress((void**)&v,  g_v);

    // ---- build CSR once per call (graph is layer-invariant) ----
    csr_zero_kernel<<<(NN + 255) / 256, 256>>>();
    csr_hist_kernel<<<(EE + 255) / 256, 256>>>(dstp);
    csr_scan1_kernel<<<SCAN_NBLK, 256>>>();
    csr_scan2_kernel<<<1, 256>>>();
    csr_scan3b_kernel<<<SCAN_NBLK, 256>>>();
    csr_fill_kernel<<<(EE + 255) / 256, 256>>>(srcp, dstp);

    const float* hin = x;
    int K = IN_F;
    float* bufs[2] = { hA, hB };

    for (int l = 0; l < NLAYERS; l++) {
        const float *Wq_l, *Wk_l, *Wv_l, *Ws_l, *bq_l, *bk_l, *bv_l, *bs_l;
        if (l == 0) {
            Wq_l = Wq0; Wk_l = Wk0; Wv_l = Wv0; Ws_l = Ws0;
            bq_l = bq0; bk_l = bk0; bv_l = bv0; bs_l = bs0;
        } else {
            size_t wo = (size_t)(l - 1) * HCF * HCF;
            size_t bo = (size_t)(l - 1) * HCF;
            Wq_l = Wq + wo; Wk_l = Wk + wo; Wv_l = Wv + wo; Ws_l = Ws + wo;
            bq_l = bq + bo; bk_l = bk + bo; bv_l = bv + bo; bs_l = bs + bo;
        }
        float* hout = bufs[l & 1];

        dim3 ggrid((NN + BM - 1) / BM, HCF / BN, 4);
        sgemm4_tf32<<<ggrid, 256, SMEM_BYTES>>>(hin, K, NN, (l > 0) ? 1 : 0,
                               Wq_l, Wk_l, Wv_l, Ws_l,
                               bq_l, bk_l, bv_l, bs_l,
                               q, k, v, hout);

        attn_fused_kernel<<<(NN * 32 + 255) / 256, 256>>>(q, k, v, hout);

        hin = hout;
        K = HCF;
    }

    zero_pool_kernel<<<(GG * HCF + 255) / 256, 256>>>();
    pool_kernel<<<NN, 256>>>(hin, batch);  // relu fused here for the last layer
    final_kernel<<<GG, OUTF>>>(Wfc, bfc, (float*)d_out);
}